// round 8
// baseline (speedup 1.0000x reference)
#include <cuda_runtime.h>

// GeneratorCell: B=128, M=32 queue rows, N=64 strokes, K=2048 stroke length
// grid=128 (1 batch/CTA), 384 threads; FIR split over n: half0 n<32, half1 n>=32
#define Bn 128
#define Mn 32
#define Nn 64
#define Kn 2048
#define NT 384
#define HT 192
#define Cn 11                      // consecutive p's per thread; 192*11 = 2112 = N + M*N
#define PAD 72                     // bottom zero pad (even, >=66 for prefetch reach)
#define EMB_SZ (PAD + Kn + 64)     // ull elements

typedef unsigned long long ull;

__device__ __forceinline__ float sigmoidf_(float x) { return 1.0f / (1.0f + __expf(-x)); }
__device__ __forceinline__ float tanhf_(float x) {   // fast tanh via MUFU exp, err ~1e-6
    float e = __expf(2.0f * x);
    return 1.0f - 2.0f / (e + 1.0f);
}

__device__ __forceinline__ ull pack2(float x, float y) {
    ull r; asm("mov.b64 %0, {%1,%2};" : "=l"(r) : "f"(x), "f"(y)); return r;
}
__device__ __forceinline__ void unpack2(ull v, float& x, float& y) {
    asm("mov.b64 {%0,%1}, %2;" : "=f"(x), "=f"(y) : "l"(v));
}
__device__ __forceinline__ ull ffma2(ull a, ull b, ull c) {   // packed f32x2 FMA (sm_100+)
    ull d; asm("fma.rn.f32x2 %0, %1, %2, %3;" : "=l"(d) : "l"(a), "l"(b), "l"(c)); return d;
}
__device__ __forceinline__ ull fadd2(ull a, ull b) {          // packed f32x2 add
    ull d; asm("add.rn.f32x2 %0, %1, %2;" : "=l"(d) : "l"(a), "l"(b)); return d;
}

__global__ __launch_bounds__(NT) void gen_cell_kernel(
    const float* __restrict__ qt1,      // [B, M, N, 2]
    const float* __restrict__ ht1,      // [B, N, 2]
    const float* __restrict__ zt,       // [B, N]
    const float* __restrict__ alpha_t,  // [B, N]
    const float* __restrict__ conv_w,   // [2, 2, M+1, 1]
    const float* __restrict__ conv_b,   // [2]
    const float* __restrict__ W_xr, const float* __restrict__ W_hr, const float* __restrict__ b_r,
    const float* __restrict__ W_xu, const float* __restrict__ W_hu, const float* __restrict__ b_u,
    const float* __restrict__ W_xn, const float* __restrict__ W_hn, const float* __restrict__ b_n,
    const float* __restrict__ lin_w,    // [N, 2N]
    const float* __restrict__ lin_b,    // [N]
    const float* __restrict__ W_emb,    // [K, 2]
    float* __restrict__ out)            // st [B,N,2] | qt [B,M,N,2] | ht [B,N,2]
{
    __shared__ __align__(16) ull    s_exy[EMB_SZ];   // interleaved (x,y) emb, zero-padded
    __shared__ __align__(16) float2 s_q[Mn * Nn];    // full q tile, reused for output
    __shared__ __align__(16) ull    s_fir[HT * Cn];  // half-1 FIR partials
    __shared__ float2 s_part[6 * Nn];                // conv partials [group][n]
    __shared__ ull    s_coef2[Nn];                   // (coef, coef) packed f32x2
    __shared__ __align__(16) float s_ht[2 * Nn];

    const int b    = blockIdx.x;
    const int tid  = threadIdx.x;
    const int lane = tid & 31;
    const int wrp  = tid >> 5;
    const float2* qf = (const float2*)(qt1 + (size_t)b * Mn * Nn * 2);

    // ============ phase 0: emb staging + q tile + conv partials (384 threads) ============
    {
        // -- staging LDGs first: 1024 float4 over 384 threads --
        const float4* we4 = (const float4*)W_emb;
        float4 e0 = we4[tid], e1 = we4[tid + 384];
        float4 e2 = make_float4(0.f, 0.f, 0.f, 0.f);
        if (tid < 256) e2 = we4[tid + 768];

        // -- conv input loads: 6 tap groups x 6 taps (h = g*6+k, h<=32; 32 = ht1 row) --
        const int n = tid & 63;          // stroke
        const int g = tid >> 6;          // tap group 0..5
        float2 v[6];
        #pragma unroll
        for (int k = 0; k < 6; k++) {
            const int h = g * 6 + k;
            if (h < 32)       v[k] = qf[h * Nn + n];
            else if (h == 32) v[k] = ((const float2*)ht1)[b * Nn + n];
            else              v[k] = make_float2(0.f, 0.f);
        }

        // -- zero the emb pads --
        if (tid < PAD) s_exy[tid] = 0ULL;
        if (tid >= HT && tid < HT + 64) s_exy[PAD + Kn + (tid - HT)] = 0ULL;

        // -- store staged emb (interleaved, STS.128) --
        float4* exy4 = (float4*)(s_exy + PAD);
        exy4[tid] = e0;  exy4[tid + 384] = e1;
        if (tid < 256) exy4[tid + 768] = e2;

        // -- stash q tile for output assembly --
        #pragma unroll
        for (int k = 0; k < 6; k++) {
            const int h = g * 6 + k;
            if (h < 32) s_q[h * Nn + n] = v[k];
        }

        // -- conv partial sums, dual chains --
        float p0a = 0.f, p0b = 0.f, p1a = 0.f, p1b = 0.f;
        #pragma unroll
        for (int k = 0; k < 6; k++) {
            const int h = g * 6 + k;
            if (h < 33) {
                const float wa = conv_w[h],      wb = conv_w[33 + h];
                const float wc = conv_w[66 + h], wd = conv_w[99 + h];
                if (k & 1) {
                    p0b = fmaf(v[k].x, wa, fmaf(v[k].y, wb, p0b));
                    p1b = fmaf(v[k].x, wc, fmaf(v[k].y, wd, p1b));
                } else {
                    p0a = fmaf(v[k].x, wa, fmaf(v[k].y, wb, p0a));
                    p1a = fmaf(v[k].x, wc, fmaf(v[k].y, wd, p1a));
                }
            }
        }
        s_part[g * Nn + n] = make_float2(p0a + p0b, p1a + p1b);
    }
    __syncthreads();

    // ---- preload lin_w row slices (LDG latency hides under GRU + FIR preload) ----
    float4 lv[6];
    {
        const float4* lw4 = (const float4*)lin_w;             // [64 rows][32 float4]
        #pragma unroll
        for (int k = 0; k < 6; k++) {
            const int row = wrp * 6 + k;                      // 12 warps x 6 > 64
            lv[k] = (row < Nn) ? lw4[row * 32 + lane]
                               : make_float4(0.f, 0.f, 0.f, 0.f);
        }
    }

    // ---- FIR setup + window preload (depends only on s_exy, ready now) ----
    const int half  = (tid >= HT) ? 1 : 0;
    const int t     = tid - half * HT;            // 0..191
    const int p0    = t * Cn;
    const int nbase = half * 32;                  // n range [nbase, nbase+32)
    ull acc[Cn], w[Cn];
    #pragma unroll
    for (int i = 0; i < Cn; i++) {
        w[i] = s_exy[PAD + p0 + i - nbase];
        acc[i] = 0ULL;
    }
    ull nxt = s_exy[PAD + p0 - nbase - 1];

    // ============ phase 1: GRU per stroke (tid<64; short tail) ============
    if (tid < 64) {
        const int n = tid;
        const float2 hv = ((const float2*)ht1)[b * Nn + n];   // L1 hit
        float h0 = conv_b[0], h1 = conv_b[1];
        #pragma unroll
        for (int g = 0; g < 6; g++) {
            const float2 p = s_part[g * Nn + n];
            h0 += p.x; h1 += p.y;
        }

        const float x0 = zt[b * Nn + n];
        const float x1 = alpha_t[b * Nn + n];

        float r0 = sigmoidf_(fmaf(x0, W_xr[0], fmaf(x1, W_xr[2], fmaf(h0, W_hr[0], fmaf(h1, W_hr[2], b_r[0])))));
        float r1 = sigmoidf_(fmaf(x0, W_xr[1], fmaf(x1, W_xr[3], fmaf(h0, W_hr[1], fmaf(h1, W_hr[3], b_r[1])))));
        float u0 = sigmoidf_(fmaf(x0, W_xu[0], fmaf(x1, W_xu[2], fmaf(h0, W_hu[0], fmaf(h1, W_hu[2], b_u[0])))));
        float u1 = sigmoidf_(fmaf(x0, W_xu[1], fmaf(x1, W_xu[3], fmaf(h0, W_hu[1], fmaf(h1, W_hu[3], b_u[1])))));

        const float rh0 = r0 * h0, rh1 = r1 * h1;
        float nt0 = tanhf_(fmaf(x0, W_xn[0], fmaf(x1, W_xn[2], fmaf(rh0, W_hn[0], fmaf(rh1, W_hn[2], b_n[0])))));
        float nt1 = tanhf_(fmaf(x0, W_xn[1], fmaf(x1, W_xn[3], fmaf(rh0, W_hn[1], fmaf(rh1, W_hn[3], b_n[1])))));

        const float hn0 = u0 * hv.x + (1.0f - u0) * nt0;
        const float hn1 = u1 * hv.y + (1.0f - u1) * nt1;

        s_ht[2 * n + 0] = hn0;
        s_ht[2 * n + 1] = hn1;

        const size_t off_ht = (size_t)Bn * Nn * 2 + (size_t)Bn * Mn * Nn * 2;
        ((float2*)(out + off_ht))[(size_t)b * Nn + n] = make_float2(hn0, hn1);
    }
    __syncthreads();

    // ============ phase 2: coef matvec, 12 warps x 6 rows, shuffle reduce ============
    {
        const float4 ht4 = ((const float4*)s_ht)[lane];       // per-lane slice of ht vector
        #pragma unroll
        for (int k = 0; k < 6; k++) {
            const int row = wrp * 6 + k;
            if (row < Nn) {
                const float4 l = lv[k];
                float d = fmaf(l.x, ht4.x, fmaf(l.y, ht4.y, fmaf(l.z, ht4.z, l.w * ht4.w)));
                d += __shfl_xor_sync(0xffffffffu, d, 16);
                d += __shfl_xor_sync(0xffffffffu, d, 8);
                d += __shfl_xor_sync(0xffffffffu, d, 4);
                d += __shfl_xor_sync(0xffffffffu, d, 2);
                d += __shfl_xor_sync(0xffffffffu, d, 1);
                if (lane == 0) {
                    const float c = (d + lin_b[row]) * alpha_t[b * Nn + row];
                    s_coef2[row] = pack2(c, c);
                }
            }
        }
    }
    __syncthreads();

    // ============ phase 3: FIR overlap-add, n-split halves, 32 iters each ============
    #pragma unroll
    for (int n = 0; n < 32; n++) {
        const ull c2 = s_coef2[nbase + n];         // warp-uniform broadcast
        #pragma unroll
        for (int i = 0; i < Cn; i++) acc[i] = ffma2(c2, w[i], acc[i]);
        #pragma unroll
        for (int i = Cn - 1; i > 0; i--) w[i] = w[i - 1];   // renamed (full unroll)
        w[0] = nxt;
        nxt = s_exy[PAD + p0 - nbase - n - 2];     // min idx = PAD-65 = 7 >= 0
    }

    // half 1 stores partials; half 0 combines + writes output
    if (half) {
        #pragma unroll
        for (int i = 0; i < Cn; i++) s_fir[t * Cn + i] = acc[i];   // stride 11: conflict-free
    }
    __syncthreads();

    if (!half) {
        float2* st_out = (float2*)out + (size_t)b * Nn;
        float2* qt_out = (float2*)(out + (size_t)Bn * Nn * 2) + (size_t)b * Mn * Nn;
        #pragma unroll
        for (int i = 0; i < Cn; i++) {
            const int p = p0 + i;
            const ull f2 = fadd2(acc[i], s_fir[t * Cn + i]);
            float fx, fy; unpack2(f2, fx, fy);
            float2 qv = make_float2(0.0f, 0.0f);
            if (p < Mn * Nn) qv = s_q[p];          // q_shift[j] = q_flat[j+N] = q_flat[p]
            float2 r = make_float2(qv.x + fx, qv.y + fy);
            if (p < Nn) st_out[p] = r;             // st = q_row0 + f[:N]
            else        qt_out[p - Nn] = r;        // qt = q_shift + tail
        }
    }
}

extern "C" void kernel_launch(void* const* d_in, const int* in_sizes, int n_in,
                              void* d_out, int out_size) {
    const float* qt1     = (const float*)d_in[0];
    const float* ht1     = (const float*)d_in[1];
    const float* zt      = (const float*)d_in[2];
    const float* alpha_t = (const float*)d_in[3];
    const float* conv_w  = (const float*)d_in[4];
    const float* conv_b  = (const float*)d_in[5];
    const float* W_xr    = (const float*)d_in[6];
    const float* W_hr    = (const float*)d_in[7];
    const float* b_r     = (const float*)d_in[8];
    const float* W_xu    = (const float*)d_in[9];
    const float* W_hu    = (const float*)d_in[10];
    const float* b_u     = (const float*)d_in[11];
    const float* W_xn    = (const float*)d_in[12];
    const float* W_hn    = (const float*)d_in[13];
    const float* b_n     = (const float*)d_in[14];
    const float* lin_w   = (const float*)d_in[15];
    const float* lin_b   = (const float*)d_in[16];
    const float* W_emb   = (const float*)d_in[17];

    gen_cell_kernel<<<Bn, NT>>>(qt1, ht1, zt, alpha_t, conv_w, conv_b,
                                W_xr, W_hr, b_r, W_xu, W_hu, b_u,
                                W_xn, W_hn, b_n, lin_w, lin_b, W_emb,
                                (float*)d_out);
}